// round 13
// baseline (speedup 1.0000x reference)
#include <cuda_runtime.h>

#define B_   2
#define N_   1024
#define FIN  128
#define FOUT 64
#define KH   64            // k-half for split-K gemm
#define CCH  8             // j-chunks
#define JC   (N_/CCH)      // 128 j per chunk
#define RPB  32            // i-rows per block (128 threads, 4 per row)

// Scratch (static device globals; no runtime allocation allowed)
__device__ __align__(16) float g_xwp[2*B_*N_*FOUT];              // 1 MB: two K-half partials
__device__ __align__(16) float g_pacc[CCH*B_*N_*FOUT];           // 4 MB partial acc
__device__ float g_pdeg[CCH*B_*N_];                              // partial degree

// ---- packed fp32x2 helpers (Blackwell-only) ----
static __device__ __forceinline__ unsigned long long f2add(unsigned long long a, unsigned long long b){
    unsigned long long r; asm("add.rn.f32x2 %0, %1, %2;" : "=l"(r) : "l"(a), "l"(b)); return r;
}
static __device__ __forceinline__ unsigned long long f2fma(unsigned long long a, unsigned long long b, unsigned long long c){
    unsigned long long r; asm("fma.rn.f32x2 %0, %1, %2, %3;" : "=l"(r) : "l"(a), "l"(b), "l"(c)); return r;
}
static __device__ __forceinline__ unsigned long long packf2(float lo, float hi){
    unsigned long long r; asm("mov.b64 %0, {%1, %2};" : "=l"(r) : "f"(lo), "f"(hi)); return r;
}
static __device__ __forceinline__ void unpackf2(unsigned long long v, float& lo, float& hi){
    asm("mov.b64 {%0, %1}, %2;" : "=f"(lo), "=f"(hi) : "l"(v));
}
// non-volatile 128-bit shared load; result kept in regs and reused by both
// the diff pass and the fma pass (this kills the pass-2 LDS reload).
static __device__ __forceinline__ ulonglong2 lds_v2u64(unsigned addr){
    ulonglong2 r;
    asm("ld.shared.v2.b64 {%0, %1}, [%2];" : "=l"(r.x), "=l"(r.y) : "r"(addr));
    return r;
}

// ---------------------------------------------------------------------------
// Kernel A: split-K GEMM. grid (128 rowblocks, 2 k-halves), 256 thr, 16 rows.
// Writes partial xw into g_xwp[kh]; consumers sum the two halves.
// ---------------------------------------------------------------------------
__global__ __launch_bounds__(256) void k_gemm(const float* __restrict__ x,
                                              const float* __restrict__ w){
    __shared__ __align__(16) float4 sW4[KH*(FOUT/4)];   // 16 KB (k-half of W)
    __shared__ __align__(16) float  sX[16*KH];          // 4 KB (16 rows, k-half)
    int tid = threadIdx.x;
    int kh  = blockIdx.y;
    int row0 = blockIdx.x * 16;
    // stage W half (contiguous 16 KB)
    {
        const float4* w4 = reinterpret_cast<const float4*>(w) + kh*(KH*FOUT/4);
        #pragma unroll
        for (int q = 0; q < (KH*FOUT/4)/256; q++)
            sW4[q*256 + tid] = w4[q*256 + tid];
    }
    // stage x half: 16 rows x 64 k  (1 float4 per thread)
    {
        int rr = tid >> 4, cc = tid & 15;
        reinterpret_cast<float4*>(sX)[tid] =
            *reinterpret_cast<const float4*>(x + (size_t)(row0+rr)*FIN + kh*KH + cc*4);
    }
    __syncthreads();

    int f4 = tid & 15;
    int r  = tid >> 4;
    float4 acc = make_float4(0.f, 0.f, 0.f, 0.f);
    const float* xr = &sX[r*KH];
    #pragma unroll 8
    for (int k = 0; k < KH; k++){
        float  xv = xr[k];
        float4 wv = sW4[k*(FOUT/4) + f4];
        acc.x = fmaf(xv, wv.x, acc.x);
        acc.y = fmaf(xv, wv.y, acc.y);
        acc.z = fmaf(xv, wv.z, acc.z);
        acc.w = fmaf(xv, wv.w, acc.w);
    }
    reinterpret_cast<float4*>(g_xwp)[(size_t)kh*(B_*N_*FOUT/4) + (size_t)(row0+r)*(FOUT/4) + f4] = acc;
}

// ---------------------------------------------------------------------------
// Kernel B: pair kernel. 4 threads per i-row (16 features each), j-tile kept
// in registers across diff+fma (single LDS pass). grid (CCH=8, 64), 128 thr.
// smem = 32KB xw-tile + 16KB adj-tile = 48KB -> 4 blocks/SM, single wave.
// ---------------------------------------------------------------------------
__global__ __launch_bounds__(128, 4) void k_main(const float* __restrict__ adj){
    __shared__ __align__(16) float4 s_xw4[JC*FOUT/4];       // 32 KB, [j][f]
    __shared__ __align__(16) float4 s_adj4[(JC/4)*RPB];     // 16 KB, [jj4][i]
    int tid = threadIdx.x;
    int c   = blockIdx.x;                  // j-chunk
    int i_local = tid >> 2;
    int fh      = tid & 3;                 // feature quarter (16 feats)
    int rowflat = blockIdx.y*RPB + i_local;
    int b  = (blockIdx.y*RPB) >> 10;       // uniform within block
    int j0 = c * JC;

    // stage xw j-chunk = sum of the two K-half partials (32 KB)
    {
        const float4* A  = reinterpret_cast<const float4*>(&g_xwp[(size_t)(b*N_ + j0)*FOUT]);
        const float4* Bp = reinterpret_cast<const float4*>(&g_xwp[(size_t)B_*N_*FOUT + (size_t)(b*N_ + j0)*FOUT]);
        #pragma unroll
        for (int q = 0; q < (JC*FOUT/4)/128; q++){
            float4 u = A[q*128 + tid], v = Bp[q*128 + tid];
            u.x += v.x; u.y += v.y; u.z += v.z; u.w += v.w;
            s_xw4[q*128 + tid] = u;
        }
    }
    // stage adj tile grouped by 4 j: s_adj4[jj4][i]
    {
        int ii = tid & 31;
        int qq = tid >> 5;                 // 0..3 -> jj4 groups of 8
        int irow = (blockIdx.y*RPB + ii) & (N_ - 1);
        const float4* ar = reinterpret_cast<const float4*>(
            adj + (size_t)b*N_*N_ + (size_t)irow*N_ + j0) + qq*8;
        #pragma unroll
        for (int p = 0; p < 8; p++)
            s_adj4[(qq*8 + p)*RPB + ii] = ar[p];
    }
    // xi quarter (16 feats), negated, packed (sum of K-halves)
    unsigned long long xin[8];
    {
        const float4* A  = reinterpret_cast<const float4*>(&g_xwp[(size_t)rowflat*FOUT + fh*16]);
        const float4* Bp = reinterpret_cast<const float4*>(&g_xwp[(size_t)B_*N_*FOUT + (size_t)rowflat*FOUT + fh*16]);
        #pragma unroll
        for (int q = 0; q < 4; q++){
            float4 u = A[q], v = Bp[q];
            xin[2*q]   = packf2(-(u.x+v.x), -(u.y+v.y));
            xin[2*q+1] = packf2(-(u.z+v.z), -(u.w+v.w));
        }
    }
    __syncthreads();

    unsigned long long acc[8];
    #pragma unroll
    for (int q = 0; q < 8; q++) acc[q] = 0ULL;
    float deg = 0.f;
    const unsigned long long MASK = 0x7FFFFFFF7FFFFFFFULL;

    unsigned base = (unsigned)__cvta_generic_to_shared(s_xw4) + (unsigned)(fh*64);

    #pragma unroll 1
    for (int jj4 = 0; jj4 < JC/4; jj4++){
        float4 a4 = s_adj4[jj4*RPB + i_local];
        #pragma unroll
        for (int u = 0; u < 4; u++){
            int jj = jj4*4 + u;
            unsigned ra = base + (unsigned)(jj*(FOUT*4));
            // single LDS pass: j-quarter-row -> regs, reused by diff AND fma
            unsigned long long t[8];
            {
                ulonglong2 v0 = lds_v2u64(ra);
                ulonglong2 v1 = lds_v2u64(ra + 16);
                ulonglong2 v2 = lds_v2u64(ra + 32);
                ulonglong2 v3 = lds_v2u64(ra + 48);
                t[0]=v0.x; t[1]=v0.y; t[2]=v1.x; t[3]=v1.y;
                t[4]=v2.x; t[5]=v2.y; t[6]=v3.x; t[7]=v3.y;
            }
            // L1 quarter-distance, tree-reduced
            unsigned long long d[8];
            #pragma unroll
            for (int q = 0; q < 8; q++) d[q] = f2add(t[q], xin[q]) & MASK;
            #pragma unroll
            for (int st = 4; st >= 1; st >>= 1)
                #pragma unroll
                for (int q = 0; q < st; q++) d[q] = f2add(d[q], d[q+st]);
            float lo, hi; unpackf2(d[0], lo, hi);
            float sh = lo + hi;
            // combine the 4 feature-quarters
            sh += __shfl_xor_sync(0xffffffffu, sh, 1);
            float s = sh + __shfl_xor_sync(0xffffffffu, sh, 2);

            float a  = (u==0) ? a4.x : (u==1) ? a4.y : (u==2) ? a4.z : a4.w;
            float wv = __fdividef(a, fmaxf(s, 1e-3f));
            deg += wv;
            unsigned long long w2 = packf2(wv, wv);

            #pragma unroll
            for (int q = 0; q < 8; q++) acc[q] = f2fma(w2, t[q], acc[q]);
        }
    }

    // write partials (this thread's 16-feature quarter)
    float* dp = &g_pacc[(size_t)c*(B_*N_*FOUT) + (size_t)rowflat*FOUT + fh*16];
    #pragma unroll
    for (int q = 0; q < 4; q++){
        float l0, h0, l1, h1;
        unpackf2(acc[2*q],   l0, h0);
        unpackf2(acc[2*q+1], l1, h1);
        float4 o; o.x = l0; o.y = h0; o.z = l1; o.w = h1;
        reinterpret_cast<float4*>(dp)[q] = o;
    }
    if (fh == 0) g_pdeg[c*(B_*N_) + rowflat] = deg;
}

// ---------------------------------------------------------------------------
// Kernel C: out = xw*(1-deg) + sum_c pacc + bias.  32768 threads, float4 each.
// ---------------------------------------------------------------------------
__global__ __launch_bounds__(256) void k_fin(const float* __restrict__ bias,
                                             float* __restrict__ out){
    int gid = blockIdx.x*256 + threadIdx.x;   // 0..32767
    int r = gid >> 4;                         // flat row 0..2047
    int q = gid & 15;                         // float4 index within F=64

    float deg = 0.f;
    #pragma unroll
    for (int c = 0; c < CCH; c++) deg += g_pdeg[c*(B_*N_) + r];

    float4 acc = make_float4(0.f, 0.f, 0.f, 0.f);
    #pragma unroll
    for (int c = 0; c < CCH; c++){
        float4 v = reinterpret_cast<const float4*>(g_pacc)[(size_t)c*(B_*N_*FOUT/4) + r*16 + q];
        acc.x += v.x; acc.y += v.y; acc.z += v.z; acc.w += v.w;
    }
    float4 xa = reinterpret_cast<const float4*>(g_xwp)[r*16 + q];
    float4 xb = reinterpret_cast<const float4*>(g_xwp)[(B_*N_*FOUT/4) + r*16 + q];
    float4 xw4; xw4.x = xa.x+xb.x; xw4.y = xa.y+xb.y; xw4.z = xa.z+xb.z; xw4.w = xa.w+xb.w;
    float4 b4  = reinterpret_cast<const float4*>(bias)[q];
    float om = 1.f - deg;
    float4 o;
    o.x = fmaf(xw4.x, om, acc.x) + b4.x;
    o.y = fmaf(xw4.y, om, acc.y) + b4.y;
    o.z = fmaf(xw4.z, om, acc.z) + b4.z;
    o.w = fmaf(xw4.w, om, acc.w) + b4.w;
    reinterpret_cast<float4*>(out)[gid] = o;
}

// ---------------------------------------------------------------------------
extern "C" void kernel_launch(void* const* d_in, const int* in_sizes, int n_in,
                              void* d_out, int out_size){
    const float *x = nullptr, *adj = nullptr, *wt = nullptr, *bs = nullptr;
    for (int k = 0; k < n_in; k++){
        int sz = in_sizes[k];
        if      (sz == B_*N_*FIN)  x   = (const float*)d_in[k];
        else if (sz == B_*N_*N_)   adj = (const float*)d_in[k];
        else if (sz == FIN*FOUT)   wt  = (const float*)d_in[k];
        else if (sz == FOUT)       bs  = (const float*)d_in[k];
    }
    (void)out_size;
    k_gemm<<<dim3((B_*N_)/16, 2), 256>>>(x, wt);
    k_main<<<dim3(CCH, (B_*N_)/RPB), 128>>>(adj);
    k_fin<<<(B_*N_*FOUT/4)/256, 256>>>(bs, (float*)d_out);
}

// round 14
// speedup vs baseline: 1.1855x; 1.1855x over previous
#include <cuda_runtime.h>

#define B_   2
#define N_   1024
#define FIN  128
#define FOUT 64
#define KS   4             // k-splits for gemm
#define KH   (FIN/KS)      // 32
#define CCH  16            // j-chunks
#define JC   (N_/CCH)      // 64 j per chunk
#define RPB  64            // i-rows per block (128 thr: 32 row-slots x 4 fh, 2 rows/thread)

// Scratch (static device globals; no runtime allocation allowed)
__device__ __align__(16) float g_xwp[KS*B_*N_*FOUT];             // 2 MB: K-split partials
__device__ __align__(16) float g_pacc[CCH*B_*N_*FOUT];           // 8 MB partial acc
__device__ float g_pdeg[CCH*B_*N_];                              // partial degree

// ---- packed fp32x2 helpers (Blackwell-only) ----
static __device__ __forceinline__ unsigned long long f2add(unsigned long long a, unsigned long long b){
    unsigned long long r; asm("add.rn.f32x2 %0, %1, %2;" : "=l"(r) : "l"(a), "l"(b)); return r;
}
static __device__ __forceinline__ unsigned long long f2fma(unsigned long long a, unsigned long long b, unsigned long long c){
    unsigned long long r; asm("fma.rn.f32x2 %0, %1, %2, %3;" : "=l"(r) : "l"(a), "l"(b), "l"(c)); return r;
}
static __device__ __forceinline__ unsigned long long packf2(float lo, float hi){
    unsigned long long r; asm("mov.b64 %0, {%1, %2};" : "=l"(r) : "f"(lo), "f"(hi)); return r;
}
static __device__ __forceinline__ void unpackf2(unsigned long long v, float& lo, float& hi){
    asm("mov.b64 {%0, %1}, %2;" : "=f"(lo), "=f"(hi) : "l"(v));
}
static __device__ __forceinline__ ulonglong2 lds_v2u64(unsigned addr){
    ulonglong2 r;
    asm("ld.shared.v2.b64 {%0, %1}, [%2];" : "=l"(r.x), "=l"(r.y) : "r"(addr));
    return r;
}

// ---------------------------------------------------------------------------
// Kernel A: split-K(4) GEMM. grid (128, 4), 256 thr, 16 rows/block, 32-k loop.
// ---------------------------------------------------------------------------
__global__ __launch_bounds__(256) void k_gemm(const float* __restrict__ x,
                                              const float* __restrict__ w){
    __shared__ __align__(16) float4 sW4[KH*(FOUT/4)];   // 8 KB (k-quarter of W)
    __shared__ __align__(16) float  sX[16*KH];          // 2 KB
    int tid = threadIdx.x;
    int kh  = blockIdx.y;
    int row0 = blockIdx.x * 16;
    // stage W quarter (contiguous 8 KB): 512 float4 / 256 thr = 2 each
    {
        const float4* w4 = reinterpret_cast<const float4*>(w) + kh*(KH*FOUT/4);
        sW4[tid]       = w4[tid];
        sW4[256 + tid] = w4[256 + tid];
    }
    // stage x: 16 rows x 32 k = 128 float4 (first 128 threads)
    if (tid < 128){
        int rr = tid >> 3, cc = tid & 7;
        reinterpret_cast<float4*>(sX)[tid] =
            *reinterpret_cast<const float4*>(x + (size_t)(row0+rr)*FIN + kh*KH + cc*4);
    }
    __syncthreads();

    int f4 = tid & 15;
    int r  = tid >> 4;
    float4 acc = make_float4(0.f, 0.f, 0.f, 0.f);
    const float* xr = &sX[r*KH];
    #pragma unroll 8
    for (int k = 0; k < KH; k++){
        float  xv = xr[k];
        float4 wv = sW4[k*(FOUT/4) + f4];
        acc.x = fmaf(xv, wv.x, acc.x);
        acc.y = fmaf(xv, wv.y, acc.y);
        acc.z = fmaf(xv, wv.z, acc.z);
        acc.w = fmaf(xv, wv.w, acc.w);
    }
    reinterpret_cast<float4*>(g_xwp)[(size_t)kh*(B_*N_*FOUT/4) + (size_t)(row0+r)*(FOUT/4) + f4] = acc;
}

// ---------------------------------------------------------------------------
// Kernel B: pair kernel with 2-row register blocking.
// 128 thr = 32 row-slots x 4 feature-quarters; thread handles rows (s, s+32),
// 16 features each. Single LDS pass: j-quarter-row t[8] reused by BOTH rows'
// diff and fma (halves smem traffic vs 1-row blocking).
// grid (16, 32), smem 32KB -> ~3.5 blocks/SM, 14 warps/SM.
// ---------------------------------------------------------------------------
__global__ __launch_bounds__(128) void k_main(const float* __restrict__ adj){
    __shared__ __align__(16) float4 s_xw4[JC*FOUT/4];    // 16 KB, [j][f]
    __shared__ float s_adjT[JC*RPB];                     // 16 KB, [jj][i_local]
    int tid = threadIdx.x;
    int c   = blockIdx.x;
    int i_slot = tid >> 2;                 // 0..31
    int fh     = tid & 3;                  // feature quarter
    int rowA = blockIdx.y*RPB + i_slot;    // flat row (b*N+i), 0..2047
    int rowB = rowA + 32;
    int b  = (blockIdx.y*RPB) >> 10;       // uniform in block
    int j0 = c * JC;

    // stage xw j-chunk = sum of KS k-split partials (16 KB)
    {
        const float4* base = reinterpret_cast<const float4*>(g_xwp) + (size_t)(b*N_ + j0)*(FOUT/4);
        #pragma unroll
        for (int q = 0; q < (JC*FOUT/4)/128; q++){
            float4 u = base[q*128 + tid];
            #pragma unroll
            for (int p = 1; p < KS; p++){
                float4 v = base[(size_t)p*(B_*N_*FOUT/4) + q*128 + tid];
                u.x += v.x; u.y += v.y; u.z += v.z; u.w += v.w;
            }
            s_xw4[q*128 + tid] = u;
        }
    }
    // stage adj tile transposed: thread (r=tid>>1, h=tid&1) loads 32 floats of row r
    {
        int r = tid >> 1, h = tid & 1;
        int irow = (blockIdx.y*RPB + r) & (N_ - 1);
        const float4* ar = reinterpret_cast<const float4*>(
            adj + (size_t)b*N_*N_ + (size_t)irow*N_ + j0 + h*32);
        #pragma unroll
        for (int q = 0; q < 8; q++){
            float4 v = ar[q];
            s_adjT[(h*32 + 4*q+0)*RPB + r] = v.x;
            s_adjT[(h*32 + 4*q+1)*RPB + r] = v.y;
            s_adjT[(h*32 + 4*q+2)*RPB + r] = v.z;
            s_adjT[(h*32 + 4*q+3)*RPB + r] = v.w;
        }
    }
    // xi quarters for both rows (sum KS partials), negated, packed
    unsigned long long xinA[8], xinB[8];
    #pragma unroll
    for (int rr = 0; rr < 2; rr++){
        int row = rr ? rowB : rowA;
        unsigned long long* xin = rr ? xinB : xinA;
        const float4* base = reinterpret_cast<const float4*>(g_xwp) + (size_t)row*(FOUT/4) + fh*4;
        #pragma unroll
        for (int q = 0; q < 4; q++){
            float4 u = base[q];
            #pragma unroll
            for (int p = 1; p < KS; p++){
                float4 v = base[(size_t)p*(B_*N_*FOUT/4) + q];
                u.x += v.x; u.y += v.y; u.z += v.z; u.w += v.w;
            }
            xin[2*q]   = packf2(-u.x, -u.y);
            xin[2*q+1] = packf2(-u.z, -u.w);
        }
    }
    __syncthreads();

    unsigned long long accA[8], accB[8];
    #pragma unroll
    for (int q = 0; q < 8; q++){ accA[q] = 0ULL; accB[q] = 0ULL; }
    float degA = 0.f, degB = 0.f;
    const unsigned long long MASK = 0x7FFFFFFF7FFFFFFFULL;

    unsigned base = (unsigned)__cvta_generic_to_shared(s_xw4) + (unsigned)(fh*64);

    #pragma unroll 1
    for (int jj = 0; jj < JC; jj++){
        unsigned ra = base + (unsigned)(jj*(FOUT*4));
        // one LDS pass: j-quarter-row, reused by both rows
        unsigned long long t[8];
        {
            ulonglong2 v0 = lds_v2u64(ra);
            ulonglong2 v1 = lds_v2u64(ra + 16);
            ulonglong2 v2 = lds_v2u64(ra + 32);
            ulonglong2 v3 = lds_v2u64(ra + 48);
            t[0]=v0.x; t[1]=v0.y; t[2]=v1.x; t[3]=v1.y;
            t[4]=v2.x; t[5]=v2.y; t[6]=v3.x; t[7]=v3.y;
        }
        // ---- row A ----
        {
            unsigned long long d[8];
            #pragma unroll
            for (int q = 0; q < 8; q++) d[q] = f2add(t[q], xinA[q]) & MASK;
            #pragma unroll
            for (int st = 4; st >= 1; st >>= 1)
                #pragma unroll
                for (int q = 0; q < st; q++) d[q] = f2add(d[q], d[q+st]);
            float lo, hi; unpackf2(d[0], lo, hi);
            float sh = lo + hi;
            sh += __shfl_xor_sync(0xffffffffu, sh, 1);
            float s = sh + __shfl_xor_sync(0xffffffffu, sh, 2);
            float a  = s_adjT[jj*RPB + i_slot];
            float wv = __fdividef(a, fmaxf(s, 1e-3f));
            degA += wv;
            unsigned long long w2 = packf2(wv, wv);
            #pragma unroll
            for (int q = 0; q < 8; q++) accA[q] = f2fma(w2, t[q], accA[q]);
        }
        // ---- row B ----
        {
            unsigned long long d[8];
            #pragma unroll
            for (int q = 0; q < 8; q++) d[q] = f2add(t[q], xinB[q]) & MASK;
            #pragma unroll
            for (int st = 4; st >= 1; st >>= 1)
                #pragma unroll
                for (int q = 0; q < st; q++) d[q] = f2add(d[q], d[q+st]);
            float lo, hi; unpackf2(d[0], lo, hi);
            float sh = lo + hi;
            sh += __shfl_xor_sync(0xffffffffu, sh, 1);
            float s = sh + __shfl_xor_sync(0xffffffffu, sh, 2);
            float a  = s_adjT[jj*RPB + i_slot + 32];
            float wv = __fdividef(a, fmaxf(s, 1e-3f));
            degB += wv;
            unsigned long long w2 = packf2(wv, wv);
            #pragma unroll
            for (int q = 0; q < 8; q++) accB[q] = f2fma(w2, t[q], accB[q]);
        }
    }

    // write partials (16-feature quarters of both rows)
    {
        float* dp = &g_pacc[(size_t)c*(B_*N_*FOUT) + (size_t)rowA*FOUT + fh*16];
        #pragma unroll
        for (int q = 0; q < 4; q++){
            float l0,h0,l1,h1;
            unpackf2(accA[2*q], l0,h0); unpackf2(accA[2*q+1], l1,h1);
            float4 o; o.x=l0; o.y=h0; o.z=l1; o.w=h1;
            reinterpret_cast<float4*>(dp)[q] = o;
        }
    }
    {
        float* dp = &g_pacc[(size_t)c*(B_*N_*FOUT) + (size_t)rowB*FOUT + fh*16];
        #pragma unroll
        for (int q = 0; q < 4; q++){
            float l0,h0,l1,h1;
            unpackf2(accB[2*q], l0,h0); unpackf2(accB[2*q+1], l1,h1);
            float4 o; o.x=l0; o.y=h0; o.z=l1; o.w=h1;
            reinterpret_cast<float4*>(dp)[q] = o;
        }
    }
    if (fh == 0){
        g_pdeg[c*(B_*N_) + rowA] = degA;
        g_pdeg[c*(B_*N_) + rowB] = degB;
    }
}

// ---------------------------------------------------------------------------
// Kernel C: out = xw*(1-deg) + sum_c pacc + bias.  32768 threads, float4 each.
// ---------------------------------------------------------------------------
__global__ __launch_bounds__(256) void k_fin(const float* __restrict__ bias,
                                             float* __restrict__ out){
    int gid = blockIdx.x*256 + threadIdx.x;   // 0..32767
    int r = gid >> 4;                         // flat row 0..2047
    int q = gid & 15;                         // float4 index within F=64

    float deg = 0.f;
    #pragma unroll
    for (int c = 0; c < CCH; c++) deg += g_pdeg[c*(B_*N_) + r];

    float4 acc = make_float4(0.f, 0.f, 0.f, 0.f);
    #pragma unroll
    for (int c = 0; c < CCH; c++){
        float4 v = reinterpret_cast<const float4*>(g_pacc)[(size_t)c*(B_*N_*FOUT/4) + r*16 + q];
        acc.x += v.x; acc.y += v.y; acc.z += v.z; acc.w += v.w;
    }
    float4 xw4 = reinterpret_cast<const float4*>(g_xwp)[r*16 + q];
    #pragma unroll
    for (int p = 1; p < KS; p++){
        float4 v = reinterpret_cast<const float4*>(g_xwp)[(size_t)p*(B_*N_*FOUT/4) + r*16 + q];
        xw4.x += v.x; xw4.y += v.y; xw4.z += v.z; xw4.w += v.w;
    }
    float4 b4  = reinterpret_cast<const float4*>(bias)[q];
    float om = 1.f - deg;
    float4 o;
    o.x = fmaf(xw4.x, om, acc.x) + b4.x;
    o.y = fmaf(xw4.y, om, acc.y) + b4.y;
    o.z = fmaf(xw4.z, om, acc.z) + b4.z;
    o.w = fmaf(xw4.w, om, acc.w) + b4.w;
    reinterpret_cast<float4*>(out)[gid] = o;
}

// ---------------------------------------------------------------------------
extern "C" void kernel_launch(void* const* d_in, const int* in_sizes, int n_in,
                              void* d_out, int out_size){
    const float *x = nullptr, *adj = nullptr, *wt = nullptr, *bs = nullptr;
    for (int k = 0; k < n_in; k++){
        int sz = in_sizes[k];
        if      (sz == B_*N_*FIN)  x   = (const float*)d_in[k];
        else if (sz == B_*N_*N_)   adj = (const float*)d_in[k];
        else if (sz == FIN*FOUT)   wt  = (const float*)d_in[k];
        else if (sz == FOUT)       bs  = (const float*)d_in[k];
    }
    (void)out_size;
    k_gemm<<<dim3((B_*N_)/16, KS), 256>>>(x, wt);
    k_main<<<dim3(CCH, (B_*N_)/RPB), 128>>>(adj);
    k_fin<<<(B_*N_*FOUT/4)/256, 256>>>(bs, (float*)d_out);
}